// round 3
// baseline (speedup 1.0000x reference)
#include <cuda_runtime.h>
#include <cstdint>
#include <math.h>

// JeffressLinear: x (64,64,128,2) f32, delay_latent (31,1) f32, weight scalar
// out (64,64,128,31) f32.
// Delays integer (frac=0 -> bernoulli dead): d = floor(relu(+-latent)) in 0..15,
// clamped per (n,c,i) by 63-argmax_t(x). LIF over shifted series -> 64-bit spike
// mask per (row,d). out[t,n,c,j] = w*(bit(m0,t)+bit(m1,t)).
// Block = (n, group of 8 channels): 1024 blocks x 256 threads.

namespace {

constexpr int T_ = 64;
constexpr int N_ = 64;
constexpr int C_ = 128;
constexpr int D_ = 31;
constexpr int ROWPITCH = 133;   // 128 data + 5 pad (odd -> conflict-free)

__global__ void __launch_bounds__(256, 6) jeffress_kernel(
    const float* __restrict__ x,
    const float* __restrict__ delay_latent,
    const float* __restrict__ wptr,
    float* __restrict__ out)
{
    __shared__ float    xs[16 * ROWPITCH];  // 16 rows (8ch x 2 comp), duplicated to 128
    __shared__ unsigned mlo[256];           // spike bits t=0..31 per (q*16+d)
    __shared__ unsigned mhi[256];           // spike bits t=32..63
    __shared__ int      clampv[16];         // 63 - argmax_t
    __shared__ int      dtab0[D_];          // floor(relu(+latent[j]))
    __shared__ int      dtab1[D_];          // floor(relu(-latent[j]))

    const int tid = threadIdx.x;
    const int b   = blockIdx.x;
    const int n   = b >> 4;
    const int cg  = b & 15;
    const int c0  = cg * 8;

    if (tid < D_) {
        float dl = delay_latent[tid];
        dtab0[tid] = (int)floorf(fmaxf(dl, 0.0f));
        dtab1[tid] = (int)floorf(fmaxf(-dl, 0.0f));
    }

    // ---- Phase 1: load x slice (64 t x 16 q), duplicated rows ----
    const float* xb = x + ((size_t)n * C_ + c0) * 2;
#pragma unroll
    for (int k = 0; k < 4; ++k) {
        int idx = tid + k * 256;    // 0..1023
        int t = idx >> 4;
        int q = idx & 15;
        float v = xb[(size_t)t * (N_ * C_ * 2) + q];
        xs[q * ROWPITCH + t]      = v;
        xs[q * ROWPITCH + 64 + t] = v;
    }
    __syncthreads();

    // ---- Phase 2a: LIF, one (q,d) run per thread ----
    {
        int d = tid & 15;
        int q = tid >> 4;
        const float* src = xs + q * ROWPITCH + (64 - d);  // wrap-free circular shift
        unsigned lo = 0u, hi = 0u;
        float v = 0.0f;
#pragma unroll
        for (int t = 0; t < 32; ++t) {
            float xt = src[t];
            v = v + (xt - v) * 0.5f;          // exact reference arithmetic order
            if (v >= 1.0f) { lo |= (1u << t); v = 0.0f; }
        }
#pragma unroll
        for (int t = 0; t < 32; ++t) {
            float xt = src[32 + t];
            v = v + (xt - v) * 0.5f;
            if (v >= 1.0f) { hi |= (1u << t); v = 0.0f; }
        }
        mlo[tid] = lo;
        mhi[tid] = hi;
    }

    // ---- Phase 2b: parallel argmax per row (first occurrence of max) ----
    // 16 threads/row, 4 elems each, shfl-reduce width 16 (strict > keeps first).
    {
        int q      = tid >> 4;
        int lane16 = tid & 15;
        const float* row = xs + q * ROWPITCH;
        int   t0   = lane16 * 4;
        float best = row[t0];
        int   bi   = t0;
#pragma unroll
        for (int t = 1; t < 4; ++t) {
            float v = row[t0 + t];
            if (v > best) { best = v; bi = t0 + t; }
        }
#pragma unroll
        for (int off = 8; off >= 1; off >>= 1) {
            float ov = __shfl_down_sync(0xffffffffu, best, off, 16);
            int   oi = __shfl_down_sync(0xffffffffu, bi,   off, 16);
            if (ov > best) { best = ov; bi = oi; }   // higher-t only on strict >
        }
        if (lane16 == 0) clampv[q] = (T_ - 1) - bi;
    }
    __syncthreads();

    // ---- Phase 3: expand bits -> fp32, coalesced float4 stores ----
    // 8ch*31j = 248 floats = 62 float4 per t. thread = (t-quarter, col); 16 t each.
    if (tid < 248) {
        const int tq  = tid / 62;        // 0..3 -> t in [tq*16, tq*16+16)
        const int col = tid - tq * 62;   // 0..61
        const int sh  = (tq & 1) * 16;
        const bool hiHalf = (tq >= 2);

        unsigned orw[4], andw[4];
#pragma unroll
        for (int kk = 0; kk < 4; ++kk) {
            int cj = col * 4 + kk;
            int c = cj / 31;
            int j = cj - c * 31;
            int q0 = c * 2;
            int d0 = min(dtab0[j], clampv[q0]);
            int d1 = min(dtab1[j], clampv[q0 + 1]);
            unsigned a = hiHalf ? mhi[q0 * 16 + d0] : mlo[q0 * 16 + d0];
            unsigned bm = hiHalf ? mhi[(q0 + 1) * 16 + d1] : mlo[(q0 + 1) * 16 + d1];
            orw[kk]  = (a | bm) >> sh;
            andw[kk] = (a & bm) >> sh;
        }
        unsigned any = (orw[0] | orw[1] | orw[2] | orw[3]) & 0xffffu;

        // float4 index: (t*64 + n)*992 + cg*62 + col, t = tq*16 + tt
        float4* op = reinterpret_cast<float4*>(out)
                   + ((size_t)(tq * 16) * 64 + n) * 992 + (size_t)cg * 62 + col;
        const size_t s4 = 64 * 992;      // per-t float4 stride

        if (any == 0u) {                 // no spikes in these 4 cols, this t-quarter
            const float4 z = make_float4(0.f, 0.f, 0.f, 0.f);
#pragma unroll
            for (int tt = 0; tt < 16; ++tt) { *op = z; op += s4; }
        } else {                         // general path: {0, w, 2w} exponent trick
            const unsigned PW = __float_as_uint(*wptr);
#pragma unroll
            for (int tt = 0; tt < 16; ++tt) {
                float4 v4;
                v4.x = __uint_as_float((orw[0] & 1u) * PW + (andw[0] & 1u) * 0x800000u);
                v4.y = __uint_as_float((orw[1] & 1u) * PW + (andw[1] & 1u) * 0x800000u);
                v4.z = __uint_as_float((orw[2] & 1u) * PW + (andw[2] & 1u) * 0x800000u);
                v4.w = __uint_as_float((orw[3] & 1u) * PW + (andw[3] & 1u) * 0x800000u);
                orw[0] >>= 1; andw[0] >>= 1; orw[1] >>= 1; andw[1] >>= 1;
                orw[2] >>= 1; andw[2] >>= 1; orw[3] >>= 1; andw[3] >>= 1;
                *op = v4; op += s4;
            }
        }
    }
}

} // namespace

extern "C" void kernel_launch(void* const* d_in, const int* in_sizes, int n_in,
                              void* d_out, int out_size) {
    const float* x  = (const float*)d_in[0];   // (64,64,128,2)
    const float* dl = (const float*)d_in[1];   // (31,1)
    const float* w  = (const float*)d_in[2];   // scalar
    float* out = (float*)d_out;                // (64,64,128,31)
    jeffress_kernel<<<1024, 256>>>(x, dl, w, out);
}

// round 4
// speedup vs baseline: 1.1233x; 1.1233x over previous
#include <cuda_runtime.h>
#include <cstdint>
#include <math.h>

// JeffressLinear: x (64,64,128,2) f32, delay_latent (31,1) f32, weight scalar
// out (64,64,128,31) f32.
// Delays integer (frac=0 -> bernoulli dead): d = floor(relu(+-latent)) in 0..15,
// clamped per (n,c,i) by 63-argmax_t(x). LIF over shifted series -> 64-bit spike
// mask per (row,d). out[t,n,c,j] = w*(bit(m0,t)+bit(m1,t)).
//
// KEY BOUND: v_t = (v_{t-1}+x_t)/2 <= max_t(x) + 64*ulp. If row max < 0.999,
// no spike can fire for ANY circular shift of that row -> masks provably zero
// -> that row's output is exactly 0 (clamp/argmax index into zero masks).
// Fast path writes zeros; full LIF path retained for rows with max >= 0.999.

namespace {

constexpr int T_ = 64;
constexpr int N_ = 64;
constexpr int C_ = 128;
constexpr int D_ = 31;
constexpr int ROWPITCH = 133;   // 128 data + 5 pad (odd -> conflict-free)

__global__ void __launch_bounds__(256, 6) jeffress_kernel(
    const float* __restrict__ x,
    const float* __restrict__ delay_latent,
    const float* __restrict__ wptr,
    float* __restrict__ out)
{
    __shared__ float    xs[16 * ROWPITCH];  // 16 rows (8ch x 2 comp), duplicated to 128
    __shared__ unsigned mlo[256];           // spike bits t=0..31 per (q*16+d)
    __shared__ unsigned mhi[256];           // spike bits t=32..63
    __shared__ int      clampv[16];         // 63 - argmax_t
    __shared__ int      dtab0[D_];          // floor(relu(+latent[j]))
    __shared__ int      dtab1[D_];          // floor(relu(-latent[j]))
    __shared__ int      spikeflag;          // any row with max >= 0.999 ?

    const int tid = threadIdx.x;
    const int b   = blockIdx.x;
    const int n   = b >> 4;
    const int cg  = b & 15;
    const int c0  = cg * 8;

    if (tid == 255) spikeflag = 0;
    if (tid < D_) {
        float dl = delay_latent[tid];
        dtab0[tid] = (int)floorf(fmaxf(dl, 0.0f));
        dtab1[tid] = (int)floorf(fmaxf(-dl, 0.0f));
    }

    // ---- Phase 1: load x slice (64 t x 16 q), duplicated rows ----
    const float* xb = x + ((size_t)n * C_ + c0) * 2;
#pragma unroll
    for (int k = 0; k < 4; ++k) {
        int idx = tid + k * 256;    // 0..1023
        int t = idx >> 4;
        int q = idx & 15;
        float v = xb[(size_t)t * (N_ * C_ * 2) + q];
        xs[q * ROWPITCH + t]      = v;
        xs[q * ROWPITCH + 64 + t] = v;
    }
    __syncthreads();

    // ---- Phase 2: per-row argmax (first occurrence) + max; set spike flag --
    // 16 threads/row, 4 elems each, shfl-reduce width 16 (strict > keeps first)
    {
        int q      = tid >> 4;
        int lane16 = tid & 15;
        const float* row = xs + q * ROWPITCH;
        int   t0   = lane16 * 4;
        float best = row[t0];
        int   bi   = t0;
#pragma unroll
        for (int t = 1; t < 4; ++t) {
            float v = row[t0 + t];
            if (v > best) { best = v; bi = t0 + t; }
        }
#pragma unroll
        for (int off = 8; off >= 1; off >>= 1) {
            float ov = __shfl_down_sync(0xffffffffu, best, off, 16);
            int   oi = __shfl_down_sync(0xffffffffu, bi,   off, 16);
            if (ov > best) { best = ov; bi = oi; }   // later-t wins only on strict >
        }
        if (lane16 == 0) {
            clampv[q] = (T_ - 1) - bi;
            if (best >= 0.999f) spikeflag = 1;       // benign same-value race
        }
    }
    __syncthreads();

    if (!spikeflag) {
        // ======== FAST PATH: all masks provably zero -> write zeros ========
        // 8ch*31j = 248 floats = 62 float4 per t. thread = (t-quarter, col).
        if (tid < 248) {
            const int tq  = tid / 62;
            const int col = tid - tq * 62;
            float4* op = reinterpret_cast<float4*>(out)
                       + ((size_t)(tq * 16) * 64 + n) * 992 + (size_t)cg * 62 + col;
            const size_t s4 = 64 * 992;
            const float4 z = make_float4(0.f, 0.f, 0.f, 0.f);
#pragma unroll
            for (int tt = 0; tt < 16; ++tt) { *op = z; op += s4; }
        }
        return;
    }

    // ======== SLOW PATH (general): full LIF + mask expansion ========
    {
        int d = tid & 15;
        int q = tid >> 4;
        const float* src = xs + q * ROWPITCH + (64 - d);  // wrap-free circular shift
        unsigned lo = 0u, hi = 0u;
        float v = 0.0f;
#pragma unroll
        for (int t = 0; t < 32; ++t) {
            float xt = src[t];
            v = v + (xt - v) * 0.5f;          // exact reference arithmetic order
            if (v >= 1.0f) { lo |= (1u << t); v = 0.0f; }
        }
#pragma unroll
        for (int t = 0; t < 32; ++t) {
            float xt = src[32 + t];
            v = v + (xt - v) * 0.5f;
            if (v >= 1.0f) { hi |= (1u << t); v = 0.0f; }
        }
        mlo[tid] = lo;
        mhi[tid] = hi;
    }
    __syncthreads();

    if (tid < 248) {
        const int tq  = tid / 62;        // 0..3 -> t in [tq*16, tq*16+16)
        const int col = tid - tq * 62;   // 0..61
        const int sh  = (tq & 1) * 16;
        const bool hiHalf = (tq >= 2);

        unsigned orw[4], andw[4];
#pragma unroll
        for (int kk = 0; kk < 4; ++kk) {
            int cj = col * 4 + kk;
            int c = cj / 31;
            int j = cj - c * 31;
            int q0 = c * 2;
            int d0 = min(dtab0[j], clampv[q0]);
            int d1 = min(dtab1[j], clampv[q0 + 1]);
            unsigned a  = hiHalf ? mhi[q0 * 16 + d0]       : mlo[q0 * 16 + d0];
            unsigned bm = hiHalf ? mhi[(q0 + 1) * 16 + d1] : mlo[(q0 + 1) * 16 + d1];
            orw[kk]  = (a | bm) >> sh;
            andw[kk] = (a & bm) >> sh;
        }
        unsigned any = (orw[0] | orw[1] | orw[2] | orw[3]) & 0xffffu;

        float4* op = reinterpret_cast<float4*>(out)
                   + ((size_t)(tq * 16) * 64 + n) * 992 + (size_t)cg * 62 + col;
        const size_t s4 = 64 * 992;

        if (any == 0u) {
            const float4 z = make_float4(0.f, 0.f, 0.f, 0.f);
#pragma unroll
            for (int tt = 0; tt < 16; ++tt) { *op = z; op += s4; }
        } else {                         // {0, w, 2w} via exponent-increment trick
            const unsigned PW = __float_as_uint(*wptr);
#pragma unroll
            for (int tt = 0; tt < 16; ++tt) {
                float4 v4;
                v4.x = __uint_as_float((orw[0] & 1u) * PW + (andw[0] & 1u) * 0x800000u);
                v4.y = __uint_as_float((orw[1] & 1u) * PW + (andw[1] & 1u) * 0x800000u);
                v4.z = __uint_as_float((orw[2] & 1u) * PW + (andw[2] & 1u) * 0x800000u);
                v4.w = __uint_as_float((orw[3] & 1u) * PW + (andw[3] & 1u) * 0x800000u);
                orw[0] >>= 1; andw[0] >>= 1; orw[1] >>= 1; andw[1] >>= 1;
                orw[2] >>= 1; andw[2] >>= 1; orw[3] >>= 1; andw[3] >>= 1;
                *op = v4; op += s4;
            }
        }
    }
}

} // namespace

extern "C" void kernel_launch(void* const* d_in, const int* in_sizes, int n_in,
                              void* d_out, int out_size) {
    const float* x  = (const float*)d_in[0];   // (64,64,128,2)
    const float* dl = (const float*)d_in[1];   // (31,1)
    const float* w  = (const float*)d_in[2];   // scalar
    float* out = (float*)d_out;                // (64,64,128,31)
    jeffress_kernel<<<1024, 256>>>(x, dl, w, out);
}